// round 1
// baseline (speedup 1.0000x reference)
#include <cuda_runtime.h>
#include <math.h>

#define DDIM 512
#define BM 128
#define BN 128
#define BK 32
#define TM 8
#define TN 8

// scratch (no allocations allowed)
__device__ int   g_codes[32768];
__device__ float g_enorm[8192];
__device__ int   g_counts[8192];
__device__ float g_tokloss[32768];

__global__ void init_kernel(int C) {
    int i = blockIdx.x * blockDim.x + threadIdx.x;
    if (i < C) g_counts[i] = 0;
}

// ||e_c||^2 per code; 1 block (128 thr) per code, float4 loads
__global__ void enorm_kernel(const float* __restrict__ emb) {
    int c = blockIdx.x;
    int tid = threadIdx.x;
    float4 v = ((const float4*)(emb + (size_t)c * DDIM))[tid];
    float s = v.x * v.x + v.y * v.y + v.z * v.z + v.w * v.w;
    #pragma unroll
    for (int o = 16; o > 0; o >>= 1) s += __shfl_down_sync(0xffffffffu, s, o);
    __shared__ float ws[4];
    if ((tid & 31) == 0) ws[tid >> 5] = s;
    __syncthreads();
    if (tid == 0) g_enorm[c] = ws[0] + ws[1] + ws[2] + ws[3];
}

// Fused GEMM + argmin. Each block: 128 tokens vs all C codes.
// score(m,c) = ||e_c||^2 - 2 * dot(z_m, e_c); running per-row argmin.
__global__ void __launch_bounds__(256) argmin_kernel(
    const float* __restrict__ z, const float* __restrict__ emb, int C)
{
    __shared__ float As[BK][BM + 4];   // [k][m], padded (stride 132)
    __shared__ float Bs[BK][BN + 4];   // [k][c]
    __shared__ float Es[BN];

    const int tid = threadIdx.x;
    const int tx = tid & 15;          // code-tile column group
    const int ty = tid >> 4;          // row group
    const int m0 = blockIdx.x * BM;

    float best[TM];
    int   bidx[TM];
    #pragma unroll
    for (int i = 0; i < TM; i++) { best[i] = 3.4e38f; bidx[i] = 0; }

    for (int c0 = 0; c0 < C; c0 += BN) {
        __syncthreads();               // protect Es + smem reuse from prev tile
        if (tid < BN) Es[tid] = g_enorm[c0 + tid];

        float acc[TM][TN];
        #pragma unroll
        for (int i = 0; i < TM; i++)
            #pragma unroll
            for (int j = 0; j < TN; j++) acc[i][j] = 0.f;

        #pragma unroll 1
        for (int k0 = 0; k0 < DDIM; k0 += BK) {
            __syncthreads();
            // Load 128x32 z-tile and 128x32 e-tile (transposed into smem).
            // 1024 float4 each; thread handles f = tid + l*256.
            #pragma unroll
            for (int l = 0; l < 4; l++) {
                int f   = tid + l * 256;
                int row = f >> 3;            // 8 float4 per row
                int kq  = (f & 7) * 4;
                float4 va = *(const float4*)(z   + (size_t)(m0 + row) * DDIM + k0 + kq);
                As[kq + 0][row] = va.x; As[kq + 1][row] = va.y;
                As[kq + 2][row] = va.z; As[kq + 3][row] = va.w;
                float4 vb = *(const float4*)(emb + (size_t)(c0 + row) * DDIM + k0 + kq);
                Bs[kq + 0][row] = vb.x; Bs[kq + 1][row] = vb.y;
                Bs[kq + 2][row] = vb.z; Bs[kq + 3][row] = vb.w;
            }
            __syncthreads();

            #pragma unroll 8
            for (int kk = 0; kk < BK; kk++) {
                float4 a0 = *(const float4*)&As[kk][ty * TM];
                float4 a1 = *(const float4*)&As[kk][ty * TM + 4];
                float4 b0 = *(const float4*)&Bs[kk][tx * TN];
                float4 b1 = *(const float4*)&Bs[kk][tx * TN + 4];
                float a[TM] = {a0.x, a0.y, a0.z, a0.w, a1.x, a1.y, a1.z, a1.w};
                float b[TN] = {b0.x, b0.y, b0.z, b0.w, b1.x, b1.y, b1.z, b1.w};
                #pragma unroll
                for (int i = 0; i < TM; i++)
                    #pragma unroll
                    for (int j = 0; j < TN; j++)
                        acc[i][j] = fmaf(a[i], b[j], acc[i][j]);
            }
        }

        // epilogue: fold this code tile into running argmin
        #pragma unroll
        for (int j = 0; j < TN; j++) {
            int   cn = c0 + tx * TN + j;
            float e  = Es[tx * TN + j];
            #pragma unroll
            for (int i = 0; i < TM; i++) {
                float dd = fmaf(-2.f, acc[i][j], e);
                if (dd < best[i]) { best[i] = dd; bidx[i] = cn; }  // strict <: first-min
            }
        }
    }

    // cross-thread (tx) reduction per row, tie -> lower index (jnp.argmin semantics)
    __syncthreads();
    float* redv = &As[0][0];
    int*   redi = (int*)&Bs[0][0];
    #pragma unroll
    for (int i = 0; i < TM; i++) {
        redv[(ty * TM + i) * 16 + tx] = best[i];
        redi[(ty * TM + i) * 16 + tx] = bidx[i];
    }
    __syncthreads();
    if (tid < BM) {
        float bv = redv[tid * 16];
        int   bi = redi[tid * 16];
        #pragma unroll
        for (int t = 1; t < 16; t++) {
            float v  = redv[tid * 16 + t];
            int   ii = redi[tid * 16 + t];
            if (v < bv) { bv = v; bi = ii; }
            else if (v == bv && ii < bi) { bi = ii; }
        }
        g_codes[m0 + tid] = bi;
    }
}

// gather z_q, compute z_q_st = z + (z_q - z) exactly like reference,
// per-token loss partial (fixed-order block reduce), int histogram.
__global__ void gather_kernel(const float* __restrict__ z, const float* __restrict__ emb,
                              float* __restrict__ out, float* __restrict__ outCodes,
                              int writeCodes)
{
    int m   = blockIdx.x;
    int tid = threadIdx.x;   // 128
    int c   = g_codes[m];
    float4 zv = ((const float4*)(z   + (size_t)m * DDIM))[tid];
    float4 ev = ((const float4*)(emb + (size_t)c * DDIM))[tid];
    float4 d, s, t;
    d.x = ev.x - zv.x; d.y = ev.y - zv.y; d.z = ev.z - zv.z; d.w = ev.w - zv.w;
    s.x = zv.x + d.x;  s.y = zv.y + d.y;  s.z = zv.z + d.z;  s.w = zv.w + d.w;
    ((float4*)(out + (size_t)m * DDIM))[tid] = s;
    t.x = s.x - zv.x; t.y = s.y - zv.y; t.z = s.z - zv.z; t.w = s.w - zv.w;
    float ls = t.x * t.x + t.y * t.y + t.z * t.z + t.w * t.w;
    #pragma unroll
    for (int o = 16; o > 0; o >>= 1) ls += __shfl_down_sync(0xffffffffu, ls, o);
    __shared__ float ws[4];
    if ((tid & 31) == 0) ws[tid >> 5] = ls;
    __syncthreads();
    if (tid == 0) {
        g_tokloss[m] = ws[0] + ws[1] + ws[2] + ws[3];
        atomicAdd(&g_counts[c], 1);
        if (writeCodes) outCodes[m] = (float)c;
    }
}

// fixed-order deterministic reductions for loss + perplexity
__global__ void finalize_kernel(float* __restrict__ outStats, int M, int C, int hasStats)
{
    __shared__ float sh[1024];
    int tid = threadIdx.x;

    float s = 0.f;
    for (int i = tid; i < M; i += 1024) s += g_tokloss[i];
    sh[tid] = s; __syncthreads();
    for (int o = 512; o > 0; o >>= 1) { if (tid < o) sh[tid] += sh[tid + o]; __syncthreads(); }
    float loss = 0.25f * sh[0] / ((float)M * (float)DDIM);
    __syncthreads();

    float p = 0.f;
    float invM = 1.f / (float)M;
    for (int i = tid; i < C; i += 1024) {
        float pr = (float)g_counts[i] * invM;
        p += pr * logf(pr + 1e-10f);
    }
    sh[tid] = p; __syncthreads();
    for (int o = 512; o > 0; o >>= 1) { if (tid < o) sh[tid] += sh[tid + o]; __syncthreads(); }

    if (tid == 0 && hasStats) {
        outStats[0] = loss;
        outStats[1] = expf(-sh[0]);
    }
}

extern "C" void kernel_launch(void* const* d_in, const int* in_sizes, int n_in,
                              void* d_out, int out_size)
{
    const float* z   = (const float*)d_in[0];
    const float* emb = (const float*)d_in[1];
    float* out = (float*)d_out;

    int M = in_sizes[0] / DDIM;   // 32768
    int C = in_sizes[1] / DDIM;   // 8192

    init_kernel<<<(C + 255) / 256, 256>>>(C);
    enorm_kernel<<<C, 128>>>(emb);
    argmin_kernel<<<M / BM, 256>>>(z, emb, C);

    long long zqN = (long long)M * DDIM;
    int writeCodes = (out_size >= zqN + M) ? 1 : 0;
    float* outCodes = out + zqN;
    gather_kernel<<<M, 128>>>(z, emb, out, outCodes, writeCodes);

    int hasStats = (out_size >= zqN + M + 2) ? 1 : 0;
    finalize_kernel<<<1, 1024>>>(out + zqN + M, M, C, hasStats);
}

// round 3
// speedup vs baseline: 2.0334x; 2.0334x over previous
#include <cuda_runtime.h>
#include <cuda_bf16.h>
#include <math.h>
#include <stdint.h>

#define DDIM   512
#define MTOK   32768
#define NCODE  8192
#define MT     128       // tokens per CTA
#define NTILE  128       // codes per tile
#define BK     64        // k per pipeline chunk (bf16)
#define NCHUNK 24        // 1536 / 64
#define NSTG   3
#define MARGIN 0.25f

#define A_BYTES (MT*BK*2)       // 16KB
#define B_BYTES (NTILE*BK*2)    // 16KB
#define STG_BYTES (A_BYTES + B_BYTES)
#define DYN_SMEM (NSTG * STG_BYTES)   // 96KB

#define SWZ(o) ((o) ^ ((((o) >> 3) & 0x70)))

// ---------------- device scratch ----------------
__device__ __nv_bfloat16 g_zsplit[(size_t)MTOK * 1024];   // [m][0:512)=hi [512:1024)=lo
__device__ __nv_bfloat16 g_esplit[(size_t)NCODE * 1024];
__device__ float g_enorm[NCODE];
__device__ int   g_codes[MTOK];
__device__ int   g_counts[NCODE];
__device__ float g_tokloss[MTOK];
__device__ unsigned long long g_key[MTOK];
__device__ int   g_flaglist[MTOK];
__device__ unsigned char g_flagged[MTOK];
__device__ int   g_nflag;

// ---------------- helpers ----------------
__device__ __forceinline__ uint32_t smem_u32(const void* p) {
    return (uint32_t)__cvta_generic_to_shared(p);
}
__device__ __forceinline__ void cpasync16(uint32_t dst, const void* src) {
    asm volatile("cp.async.cg.shared.global [%0], [%1], 16;" :: "r"(dst), "l"(src) : "memory");
}
__device__ __forceinline__ void cp_commit() {
    asm volatile("cp.async.commit_group;" ::: "memory");
}
template<int N> __device__ __forceinline__ void cp_wait() {
    asm volatile("cp.async.wait_group %0;" :: "n"(N) : "memory");
}
__device__ __forceinline__ void ldsm4(uint32_t& r0, uint32_t& r1, uint32_t& r2, uint32_t& r3,
                                      uint32_t a) {
    asm volatile("ldmatrix.sync.aligned.m8n8.x4.shared.b16 {%0,%1,%2,%3}, [%4];"
                 : "=r"(r0), "=r"(r1), "=r"(r2), "=r"(r3) : "r"(a));
}
__device__ __forceinline__ void mma16816(float* c, const uint32_t* a, const uint32_t* b) {
    asm volatile(
        "mma.sync.aligned.m16n8k16.row.col.f32.bf16.bf16.f32 "
        "{%0,%1,%2,%3}, {%4,%5,%6,%7}, {%8,%9}, {%0,%1,%2,%3};"
        : "+f"(c[0]), "+f"(c[1]), "+f"(c[2]), "+f"(c[3])
        : "r"(a[0]), "r"(a[1]), "r"(a[2]), "r"(a[3]), "r"(b[0]), "r"(b[1]));
}
__device__ __forceinline__ unsigned long long packkey(float d, int c) {
    unsigned u = __float_as_uint(d);
    u = (u & 0x80000000u) ? ~u : (u | 0x80000000u);
    return ((unsigned long long)u << 32) | (unsigned)c;
}

// ---------------- setup kernels ----------------
__global__ void init_kernel() {
    int i = blockIdx.x * blockDim.x + threadIdx.x;
    if (i < NCODE) g_counts[i] = 0;
    if (i < MTOK) { g_flagged[i] = 0; g_key[i] = 0xFFFFFFFFFFFFFFFFull; }
    if (i == 0) g_nflag = 0;
}

__global__ void split_kernel(const float* __restrict__ x, __nv_bfloat16* __restrict__ out, int n) {
    int i = blockIdx.x * blockDim.x + threadIdx.x;
    if (i >= n) return;
    float v = x[i];
    __nv_bfloat16 hi = __float2bfloat16(v);
    float rem = v - __bfloat162float(hi);
    __nv_bfloat16 lo = __float2bfloat16(rem);
    size_t row = (size_t)(i >> 9), col = (size_t)(i & 511);
    out[row * 1024 + col] = hi;
    out[row * 1024 + 512 + col] = lo;
}

__global__ void enorm_kernel(const float* __restrict__ emb) {
    int c = blockIdx.x, tid = threadIdx.x;
    float4 v = ((const float4*)(emb + (size_t)c * DDIM))[tid];
    float s = v.x * v.x + v.y * v.y + v.z * v.z + v.w * v.w;
    #pragma unroll
    for (int o = 16; o > 0; o >>= 1) s += __shfl_down_sync(0xffffffffu, s, o);
    __shared__ float ws[4];
    if ((tid & 31) == 0) ws[tid >> 5] = s;
    __syncthreads();
    if (tid == 0) g_enorm[c] = ws[0] + ws[1] + ws[2] + ws[3];
}

// ---------------- fused HMMA GEMM + argmin ----------------
// CTA: 128 tokens vs all C codes, code tiles of 128.
// 8 warps: warp grid 4(M) x 2(N), warp tile 32x64.
__global__ void __launch_bounds__(256, 2) hmma_argmin_kernel(int C) {
    extern __shared__ __align__(1024) char dyn[];
    __shared__ float tb[MT][2];        // per-tile best per (row, wn)
    __shared__ float ts[MT][2];
    __shared__ int   ti[MT][2];
    __shared__ float rb[MT], rs[MT];   // running best/second
    __shared__ int   ri[MT];

    const uint32_t sb = smem_u32(dyn);
    const int tid = threadIdx.x;
    const int wid = tid >> 5, l = tid & 31;
    const int wm = wid >> 1, wn = wid & 1;   // 4 x 2 warp grid
    const int m0 = blockIdx.x * MT;
    const int nct = C / NTILE;                // 64

    if (tid < MT) { rb[tid] = 3.4e38f; rs[tid] = 3.4e38f; ri[tid] = 0; }
    __syncthreads();

    const __nv_bfloat16* Z = g_zsplit;
    const __nv_bfloat16* E = g_esplit;

    for (int t = 0; t < nct; t++) {
        const int c0 = t * NTILE;

        // ---- issue one chunk into a stage ----
        auto load_chunk = [&](int ch, int s) {
            int seg = ch >> 3, kin = (ch & 7) * 64;
            int a_k = (seg == 2 ? 512 : 0) + kin;
            int b_k = (seg == 1 ? 512 : 0) + kin;
            uint32_t abase = sb + s * STG_BYTES;
            uint32_t bbase = abase + A_BYTES;
            #pragma unroll
            for (int q = 0; q < 4; q++) {
                int f = tid + q * 256;
                int row = f >> 3, kq = (f & 7) * 8;
                cpasync16(abase + SWZ(row * 128 + kq * 2),
                          Z + ((size_t)(m0 + row) * 1024 + a_k + kq));
                cpasync16(bbase + SWZ(row * 128 + kq * 2),
                          E + ((size_t)(c0 + row) * 1024 + b_k + kq));
            }
            cp_commit();
        };

        float acc[2][8][4];
        #pragma unroll
        for (int am = 0; am < 2; am++)
            #pragma unroll
            for (int bn = 0; bn < 8; bn++)
                #pragma unroll
                for (int k = 0; k < 4; k++) acc[am][bn][k] = 0.f;

        load_chunk(0, 0);
        load_chunk(1, 1);

        for (int ch = 0; ch < NCHUNK; ch++) {
            if (ch < NCHUNK - 1) cp_wait<1>(); else cp_wait<0>();
            __syncthreads();
            if (ch + 2 < NCHUNK) load_chunk(ch + 2, (ch + 2) % NSTG);

            uint32_t abase = sb + (ch % NSTG) * STG_BYTES;
            uint32_t bbase = abase + A_BYTES;

            #pragma unroll
            for (int kk = 0; kk < 4; kk++) {
                uint32_t af[2][4];
                #pragma unroll
                for (int am = 0; am < 2; am++) {
                    int row = wm * 32 + am * 16 + (l & 7) + ((l >> 3) & 1) * 8;
                    int kb = kk * 32 + (l >> 4) * 16;
                    ldsm4(af[am][0], af[am][1], af[am][2], af[am][3],
                          abase + SWZ(row * 128 + kb));
                }
                uint32_t bf[8][2];
                #pragma unroll
                for (int bp = 0; bp < 4; bp++) {
                    int row = wn * 64 + bp * 16 + (l & 7) + (l >> 4) * 8;
                    int kb = kk * 32 + ((l >> 3) & 1) * 16;
                    ldsm4(bf[2 * bp][0], bf[2 * bp][1], bf[2 * bp + 1][0], bf[2 * bp + 1][1],
                          bbase + SWZ(row * 128 + kb));
                }
                #pragma unroll
                for (int am = 0; am < 2; am++)
                    #pragma unroll
                    for (int bn = 0; bn < 8; bn++)
                        mma16816(acc[am][bn], af[am], bf[bn]);
            }
        }

        // ---- per-tile argmin epilogue ----
        // thread holds rows: wm*32 + am*16 + h*8 + l/4 ; cols: wn*64 + bn*8 + (l&3)*2 + j
        #pragma unroll
        for (int am = 0; am < 2; am++) {
            #pragma unroll
            for (int h = 0; h < 2; h++) {
                float best = 3.4e38f, second = 3.4e38f;
                int bidx = 0;
                #pragma unroll
                for (int bn = 0; bn < 8; bn++) {
                    #pragma unroll
                    for (int j = 0; j < 2; j++) {
                        int c = c0 + wn * 64 + bn * 8 + (l & 3) * 2 + j;
                        float v = fmaf(-2.f, acc[am][bn][h * 2 + j], __ldg(&g_enorm[c]));
                        bool pr = (v < best);
                        second = pr ? best : (v < second ? v : second);
                        bidx = pr ? c : bidx;
                        best = pr ? v : best;
                    }
                }
                // merge across the 4 lanes sharing this row (lanes differ in l&3)
                #pragma unroll
                for (int o = 1; o <= 2; o <<= 1) {
                    float ob = __shfl_xor_sync(0xffffffffu, best, o);
                    float os = __shfl_xor_sync(0xffffffffu, second, o);
                    int   oi = __shfl_xor_sync(0xffffffffu, bidx, o);
                    bool take = (ob < best) || (ob == best && oi < bidx);
                    float lose = take ? best : ob;
                    bidx  = take ? oi : bidx;
                    best  = take ? ob : best;
                    second = fminf(lose, fminf(second, os));
                }
                if ((l & 3) == 0) {
                    int row = wm * 32 + am * 16 + h * 8 + (l >> 2);
                    tb[row][wn] = best; ts[row][wn] = second; ti[row][wn] = bidx;
                }
            }
        }
        __syncthreads();
        if (tid < MT) {
            float b0 = tb[tid][0], b1 = tb[tid][1];
            float s0 = ts[tid][0], s1 = ts[tid][1];
            int i0 = ti[tid][0], i1 = ti[tid][1];
            bool take = (b1 < b0) || (b1 == b0 && i1 < i0);
            float tbest = take ? b1 : b0;
            int   tidx  = take ? i1 : i0;
            float tsec  = fminf(take ? b0 : b1, fminf(s0, s1));
            // fold into running
            bool pr = (tbest < rb[tid]) || (tbest == rb[tid] && tidx < ri[tid]);
            float lose = pr ? rb[tid] : tbest;
            if (pr) { rb[tid] = tbest; ri[tid] = tidx; }
            rs[tid] = fminf(lose, fminf(rs[tid], tsec));
        }
        __syncthreads();
    }

    if (tid < MT) {
        int m = m0 + tid;
        g_codes[m] = ri[tid];
        if (rs[tid] - rb[tid] < MARGIN) {
            int slot = atomicAdd(&g_nflag, 1);
            g_flaglist[slot] = m;
            g_flagged[m] = 1;
        }
    }
}

// ---------------- exact fp32 rescore of flagged tokens ----------------
__global__ void __launch_bounds__(256) rescan_kernel(const float* __restrict__ emb,
                                                     const float* __restrict__ z) {
    int n = g_nflag;
    if (n == 0) return;
    extern __shared__ float est[];   // [512][33]
    int tid = threadIdx.x;
    int cslice = blockIdx.x & 255;
    int tg = blockIdx.x >> 8;
    int cbase = cslice * 32;
    for (int idx = tid; idx < 32 * 512; idx += 256) {
        int code = idx >> 9, k = idx & 511;
        est[k * 33 + code] = emb[(size_t)(cbase + code) * DDIM + k];
    }
    __syncthreads();
    int w = tid >> 5, lane = tid & 31;
    int c = cbase + lane;
    float en = g_enorm[c];
    for (int j = tg * 8 + w; j < n; j += 32) {
        int m = g_flaglist[j];
        const float* zr = z + (size_t)m * DDIM;
        float acc = 0.f;
        #pragma unroll 8
        for (int k = 0; k < DDIM; k++)
            acc = fmaf(__ldg(zr + k), est[k * 33 + lane], acc);
        float v = fmaf(-2.f, acc, en);
        atomicMin(&g_key[m], packkey(v, c));
    }
}

// ---------------- gather / stats ----------------
__global__ void gather_kernel(const float* __restrict__ z, const float* __restrict__ emb,
                              float* __restrict__ out, float* __restrict__ outCodes,
                              int writeCodes) {
    int m = blockIdx.x, tid = threadIdx.x;
    int c = g_codes[m];
    if (g_flagged[m]) c = (int)(g_key[m] & 0xFFFFFFFFull);
    float4 zv = ((const float4*)(z + (size_t)m * DDIM))[tid];
    float4 ev = ((const float4*)(emb + (size_t)c * DDIM))[tid];
    float4 d, s, t;
    d.x = ev.x - zv.x; d.y = ev.y - zv.y; d.z = ev.z - zv.z; d.w = ev.w - zv.w;
    s.x = zv.x + d.x;  s.y = zv.y + d.y;  s.z = zv.z + d.z;  s.w = zv.w + d.w;
    ((float4*)(out + (size_t)m * DDIM))[tid] = s;
    t.x = s.x - zv.x; t.y = s.y - zv.y; t.z = s.z - zv.z; t.w = s.w - zv.w;
    float ls = t.x * t.x + t.y * t.y + t.z * t.z + t.w * t.w;
    #pragma unroll
    for (int o = 16; o > 0; o >>= 1) ls += __shfl_down_sync(0xffffffffu, ls, o);
    __shared__ float ws[4];
    if ((tid & 31) == 0) ws[tid >> 5] = ls;
    __syncthreads();
    if (tid == 0) {
        g_tokloss[m] = ws[0] + ws[1] + ws[2] + ws[3];
        atomicAdd(&g_counts[c], 1);
        if (writeCodes) outCodes[m] = (float)c;
    }
}

__global__ void finalize_kernel(float* __restrict__ outStats, int M, int C, int hasStats) {
    __shared__ float sh[1024];
    int tid = threadIdx.x;
    float s = 0.f;
    for (int i = tid; i < M; i += 1024) s += g_tokloss[i];
    sh[tid] = s; __syncthreads();
    for (int o = 512; o > 0; o >>= 1) { if (tid < o) sh[tid] += sh[tid + o]; __syncthreads(); }
    float loss = 0.25f * sh[0] / ((float)M * (float)DDIM);
    __syncthreads();
    float p = 0.f;
    float invM = 1.f / (float)M;
    for (int i = tid; i < C; i += 1024) {
        float pr = (float)g_counts[i] * invM;
        p += pr * logf(pr + 1e-10f);
    }
    sh[tid] = p; __syncthreads();
    for (int o = 512; o > 0; o >>= 1) { if (tid < o) sh[tid] += sh[tid + o]; __syncthreads(); }
    if (tid == 0 && hasStats) {
        outStats[0] = loss;
        outStats[1] = expf(-sh[0]);
    }
}

extern "C" void kernel_launch(void* const* d_in, const int* in_sizes, int n_in,
                              void* d_out, int out_size) {
    const float* z   = (const float*)d_in[0];
    const float* emb = (const float*)d_in[1];
    float* out = (float*)d_out;

    int M = in_sizes[0] / DDIM;   // 32768
    int C = in_sizes[1] / DDIM;   // 8192

    static int attr_done = 0;
    if (!attr_done) {
        cudaFuncSetAttribute(hmma_argmin_kernel, cudaFuncAttributeMaxDynamicSharedMemorySize, DYN_SMEM);
        cudaFuncSetAttribute(rescan_kernel, cudaFuncAttributeMaxDynamicSharedMemorySize, 512 * 33 * 4);
        attr_done = 1;
    }

    init_kernel<<<(MTOK + 255) / 256, 256>>>();
    {
        __nv_bfloat16* zs; cudaGetSymbolAddress((void**)&zs, g_zsplit);
        __nv_bfloat16* es; cudaGetSymbolAddress((void**)&es, g_esplit);
        int nz = M * DDIM, ne = C * DDIM;
        split_kernel<<<(nz + 255) / 256, 256>>>(z, zs, nz);
        split_kernel<<<(ne + 255) / 256, 256>>>(emb, es, ne);
    }
    enorm_kernel<<<C, 128>>>(emb);

    hmma_argmin_kernel<<<M / MT, 256, DYN_SMEM>>>(C);

    rescan_kernel<<<1024, 256, 512 * 33 * 4>>>(emb, z);

    long long zqN = (long long)M * DDIM;
    int writeCodes = (out_size >= zqN + M) ? 1 : 0;
    gather_kernel<<<M, 128>>>(z, emb, out, out + zqN, writeCodes);

    int hasStats = (out_size >= zqN + M + 2) ? 1 : 0;
    finalize_kernel<<<1, 1024>>>(out + zqN + M, M, C, hasStats);
}

// round 4
// speedup vs baseline: 3.5947x; 1.7678x over previous
#include <cuda_runtime.h>
#include <cuda_fp16.h>
#include <math.h>
#include <stdint.h>

#define DDIM   512
#define MTOK   32768
#define NCODE  8192
#define MT     128       // tokens per CTA
#define NTILE  128       // codes per tile
#define BK     64        // k per pipeline chunk (half)
#define NCH    8         // chunks per tile (512/64)
#define NSTG   3
#define MARGIN 0.25f

#define A_BYTES (MT*BK*2)       // 16KB
#define B_BYTES (NTILE*BK*2)    // 16KB
#define STG_BYTES (A_BYTES + B_BYTES)
#define DYN_SMEM (NSTG * STG_BYTES)   // 96KB

#define SWZ(o) ((o) ^ ((((o) >> 3) & 0x70)))

// ---------------- device scratch ----------------
__device__ __half g_zh[(size_t)MTOK * DDIM];
__device__ __half g_eh[(size_t)NCODE * DDIM];
__device__ float g_enorm[NCODE];
__device__ int   g_codes[MTOK];
__device__ int   g_counts[NCODE];
__device__ float g_tokloss[MTOK];
__device__ unsigned long long g_key[MTOK];
__device__ int   g_flaglist[MTOK];
__device__ unsigned char g_flagged[MTOK];
__device__ int   g_nflag;

// ---------------- helpers ----------------
__device__ __forceinline__ uint32_t smem_u32(const void* p) {
    return (uint32_t)__cvta_generic_to_shared(p);
}
__device__ __forceinline__ void cpasync16(uint32_t dst, const void* src) {
    asm volatile("cp.async.cg.shared.global [%0], [%1], 16;" :: "r"(dst), "l"(src) : "memory");
}
__device__ __forceinline__ void cp_commit() {
    asm volatile("cp.async.commit_group;" ::: "memory");
}
template<int N> __device__ __forceinline__ void cp_wait() {
    asm volatile("cp.async.wait_group %0;" :: "n"(N) : "memory");
}
__device__ __forceinline__ void ldsm4(uint32_t& r0, uint32_t& r1, uint32_t& r2, uint32_t& r3,
                                      uint32_t a) {
    asm volatile("ldmatrix.sync.aligned.m8n8.x4.shared.b16 {%0,%1,%2,%3}, [%4];"
                 : "=r"(r0), "=r"(r1), "=r"(r2), "=r"(r3) : "r"(a));
}
__device__ __forceinline__ void mma16816(float* c, const uint32_t* a, const uint32_t* b) {
    asm volatile(
        "mma.sync.aligned.m16n8k16.row.col.f32.f16.f16.f32 "
        "{%0,%1,%2,%3}, {%4,%5,%6,%7}, {%8,%9}, {%0,%1,%2,%3};"
        : "+f"(c[0]), "+f"(c[1]), "+f"(c[2]), "+f"(c[3])
        : "r"(a[0]), "r"(a[1]), "r"(a[2]), "r"(a[3]), "r"(b[0]), "r"(b[1]));
}
__device__ __forceinline__ unsigned long long packkey(float d, int c) {
    unsigned u = __float_as_uint(d);
    u = (u & 0x80000000u) ? ~u : (u | 0x80000000u);
    return ((unsigned long long)u << 32) | (unsigned)c;
}

// ---------------- setup kernels ----------------
__global__ void init_kernel() {
    int i = blockIdx.x * blockDim.x + threadIdx.x;
    if (i < NCODE) g_counts[i] = 0;
    if (i < MTOK) { g_flagged[i] = 0; g_key[i] = 0xFFFFFFFFFFFFFFFFull; }
    if (i == 0) g_nflag = 0;
}

__global__ void convert_kernel(const float* __restrict__ x, __half* __restrict__ out, int n4) {
    int i = blockIdx.x * blockDim.x + threadIdx.x;
    if (i >= n4) return;
    float4 v = ((const float4*)x)[i];
    __half2 h0 = __floats2half2_rn(v.x, v.y);
    __half2 h1 = __floats2half2_rn(v.z, v.w);
    ((__half2*)out)[i * 2] = h0;
    ((__half2*)out)[i * 2 + 1] = h1;
}

__global__ void enorm_kernel(const float* __restrict__ emb) {
    int c = blockIdx.x, tid = threadIdx.x;
    float4 v = ((const float4*)(emb + (size_t)c * DDIM))[tid];
    float s = v.x * v.x + v.y * v.y + v.z * v.z + v.w * v.w;
    #pragma unroll
    for (int o = 16; o > 0; o >>= 1) s += __shfl_down_sync(0xffffffffu, s, o);
    __shared__ float ws[4];
    if ((tid & 31) == 0) ws[tid >> 5] = s;
    __syncthreads();
    if (tid == 0) g_enorm[c] = ws[0] + ws[1] + ws[2] + ws[3];
}

// ---------------- fused HMMA GEMM + argmin (K=512 fp16, flat pipeline) ----------------
// CTA: 128 tokens vs all C codes; 8 warps in 4(M) x 2(N); warp tile 32x64.
__global__ void __launch_bounds__(256, 2) hmma_argmin_kernel(int C) {
    extern __shared__ __align__(1024) char dyn[];
    __shared__ float tb[MT][2];
    __shared__ float ts[MT][2];
    __shared__ int   ti[MT][2];

    const uint32_t sb = smem_u32(dyn);
    const int tid = threadIdx.x;
    const int wid = tid >> 5, l = tid & 31;
    const int wm = wid >> 1, wn = wid & 1;
    const int m0 = blockIdx.x * MT;
    const int nct = C / NTILE;          // 64
    const int TOT = nct * NCH;          // 512

    const __half* Z = g_zh;
    const __half* E = g_eh;

    // running per-thread argmin state: 4 row slots (am, h)
    float rbest[4], rsec[4];
    int   ridx[4];
    #pragma unroll
    for (int r = 0; r < 4; r++) { rbest[r] = 3.4e38f; rsec[r] = 3.4e38f; ridx[r] = 0; }

    auto load_chunk = [&](int i) {
        int t = i >> 3, ch = i & 7;
        int kk0 = ch * BK;
        int c0 = t * NTILE;
        uint32_t abase = sb + (i % NSTG) * STG_BYTES;
        uint32_t bbase = abase + A_BYTES;
        #pragma unroll
        for (int q = 0; q < 4; q++) {
            int f = tid + q * 256;
            int row = f >> 3, kq = (f & 7) * 8;
            cpasync16(abase + SWZ(row * 128 + kq * 2),
                      Z + ((size_t)(m0 + row) * DDIM + kk0 + kq));
            cpasync16(bbase + SWZ(row * 128 + kq * 2),
                      E + ((size_t)(c0 + row) * DDIM + kk0 + kq));
        }
        cp_commit();
    };

    load_chunk(0);
    load_chunk(1);

    float acc[2][8][4];
    #pragma unroll
    for (int am = 0; am < 2; am++)
        #pragma unroll
        for (int bn = 0; bn < 8; bn++)
            #pragma unroll
            for (int k = 0; k < 4; k++) acc[am][bn][k] = 0.f;

    for (int i = 0; i < TOT; i++) {
        if (i + 1 < TOT) cp_wait<1>(); else cp_wait<0>();
        __syncthreads();
        if (i + 2 < TOT) load_chunk(i + 2);

        uint32_t abase = sb + (i % NSTG) * STG_BYTES;
        uint32_t bbase = abase + A_BYTES;

        #pragma unroll
        for (int kk = 0; kk < 4; kk++) {
            uint32_t af[2][4];
            #pragma unroll
            for (int am = 0; am < 2; am++) {
                int row = wm * 32 + am * 16 + (l & 7) + ((l >> 3) & 1) * 8;
                int kb = kk * 32 + (l >> 4) * 16;
                ldsm4(af[am][0], af[am][1], af[am][2], af[am][3],
                      abase + SWZ(row * 128 + kb));
            }
            uint32_t bf[8][2];
            #pragma unroll
            for (int bp = 0; bp < 4; bp++) {
                int row = wn * 64 + bp * 16 + (l & 7) + (l >> 4) * 8;
                int kb = kk * 32 + ((l >> 3) & 1) * 16;
                ldsm4(bf[2 * bp][0], bf[2 * bp][1], bf[2 * bp + 1][0], bf[2 * bp + 1][1],
                      bbase + SWZ(row * 128 + kb));
            }
            #pragma unroll
            for (int am = 0; am < 2; am++)
                #pragma unroll
                for (int bn = 0; bn < 8; bn++)
                    mma16816(acc[am][bn], af[am], bf[bn]);
        }

        if ((i & 7) == 7) {
            // tile finished: fold into running register argmin (no syncs)
            int c0 = (i >> 3) * NTILE;
            #pragma unroll
            for (int bn = 0; bn < 8; bn++) {
                #pragma unroll
                for (int j = 0; j < 2; j++) {
                    int c = c0 + wn * 64 + bn * 8 + (l & 3) * 2 + j;
                    float e = __ldg(&g_enorm[c]);
                    #pragma unroll
                    for (int am = 0; am < 2; am++) {
                        #pragma unroll
                        for (int h = 0; h < 2; h++) {
                            int r = am * 2 + h;
                            float v = fmaf(-2.f, acc[am][bn][h * 2 + j], e);
                            bool pr = v < rbest[r];
                            rsec[r] = pr ? rbest[r] : (v < rsec[r] ? v : rsec[r]);
                            ridx[r] = pr ? c : ridx[r];
                            rbest[r] = pr ? v : rbest[r];
                        }
                    }
                }
            }
            #pragma unroll
            for (int am = 0; am < 2; am++)
                #pragma unroll
                for (int bn = 0; bn < 8; bn++)
                    #pragma unroll
                    for (int k = 0; k < 4; k++) acc[am][bn][k] = 0.f;
        }
    }

    // ---- final merge: across 4 lanes of the quad, then across wn via smem ----
    #pragma unroll
    for (int r = 0; r < 4; r++) {
        float best = rbest[r], second = rsec[r];
        int bidx = ridx[r];
        #pragma unroll
        for (int o = 1; o <= 2; o <<= 1) {
            float ob = __shfl_xor_sync(0xffffffffu, best, o);
            float os = __shfl_xor_sync(0xffffffffu, second, o);
            int   oi = __shfl_xor_sync(0xffffffffu, bidx, o);
            bool take = (ob < best) || (ob == best && oi < bidx);
            float lose = take ? best : ob;
            bidx  = take ? oi : bidx;
            best  = take ? ob : best;
            second = fminf(lose, fminf(second, os));
        }
        if ((l & 3) == 0) {
            int am = r >> 1, h = r & 1;
            int row = wm * 32 + am * 16 + h * 8 + (l >> 2);
            tb[row][wn] = best; ts[row][wn] = second; ti[row][wn] = bidx;
        }
    }
    __syncthreads();
    if (tid < MT) {
        float b0 = tb[tid][0], b1 = tb[tid][1];
        float s0 = ts[tid][0], s1 = ts[tid][1];
        int i0 = ti[tid][0], i1 = ti[tid][1];
        bool take = (b1 < b0) || (b1 == b0 && i1 < i0);
        float fbest = take ? b1 : b0;
        int   fidx  = take ? i1 : i0;
        float fsec  = fminf(take ? b0 : b1, fminf(s0, s1));
        int m = m0 + tid;
        g_codes[m] = fidx;
        if (fsec - fbest < MARGIN) {
            int slot = atomicAdd(&g_nflag, 1);
            g_flaglist[slot] = m;
            g_flagged[m] = 1;
        }
    }
}

// ---------------- exact fp32 rescore of flagged tokens ----------------
__global__ void __launch_bounds__(256) rescan_kernel(const float* __restrict__ emb,
                                                     const float* __restrict__ z) {
    int n = g_nflag;
    if (n == 0) return;
    extern __shared__ float est[];   // [512][33]
    int tid = threadIdx.x;
    int cslice = blockIdx.x & 255;
    int tg = blockIdx.x >> 8;
    int cbase = cslice * 32;
    for (int idx = tid; idx < 32 * 512; idx += 256) {
        int code = idx >> 9, k = idx & 511;
        est[k * 33 + code] = emb[(size_t)(cbase + code) * DDIM + k];
    }
    __syncthreads();
    int w = tid >> 5, lane = tid & 31;
    int c = cbase + lane;
    float en = g_enorm[c];
    for (int j = tg * 8 + w; j < n; j += 32) {
        int m = g_flaglist[j];
        const float* zr = z + (size_t)m * DDIM;
        float acc = 0.f;
        #pragma unroll 8
        for (int k = 0; k < DDIM; k++)
            acc = fmaf(__ldg(zr + k), est[k * 33 + lane], acc);
        float v = fmaf(-2.f, acc, en);
        atomicMin(&g_key[m], packkey(v, c));
    }
}

// ---------------- gather / stats ----------------
__global__ void gather_kernel(const float* __restrict__ z, const float* __restrict__ emb,
                              float* __restrict__ out, float* __restrict__ outCodes,
                              int writeCodes) {
    int m = blockIdx.x, tid = threadIdx.x;
    int c = g_codes[m];
    if (g_flagged[m]) c = (int)(g_key[m] & 0xFFFFFFFFull);
    float4 zv = ((const float4*)(z + (size_t)m * DDIM))[tid];
    float4 ev = ((const float4*)(emb + (size_t)c * DDIM))[tid];
    float4 d, s, t;
    d.x = ev.x - zv.x; d.y = ev.y - zv.y; d.z = ev.z - zv.z; d.w = ev.w - zv.w;
    s.x = zv.x + d.x;  s.y = zv.y + d.y;  s.z = zv.z + d.z;  s.w = zv.w + d.w;
    ((float4*)(out + (size_t)m * DDIM))[tid] = s;
    t.x = s.x - zv.x; t.y = s.y - zv.y; t.z = s.z - zv.z; t.w = s.w - zv.w;
    float ls = t.x * t.x + t.y * t.y + t.z * t.z + t.w * t.w;
    #pragma unroll
    for (int o = 16; o > 0; o >>= 1) ls += __shfl_down_sync(0xffffffffu, ls, o);
    __shared__ float ws[4];
    if ((tid & 31) == 0) ws[tid >> 5] = ls;
    __syncthreads();
    if (tid == 0) {
        g_tokloss[m] = ws[0] + ws[1] + ws[2] + ws[3];
        atomicAdd(&g_counts[c], 1);
        if (writeCodes) outCodes[m] = (float)c;
    }
}

__global__ void finalize_kernel(float* __restrict__ outStats, int M, int C, int hasStats) {
    __shared__ float sh[1024];
    int tid = threadIdx.x;
    float s = 0.f;
    for (int i = tid; i < M; i += 1024) s += g_tokloss[i];
    sh[tid] = s; __syncthreads();
    for (int o = 512; o > 0; o >>= 1) { if (tid < o) sh[tid] += sh[tid + o]; __syncthreads(); }
    float loss = 0.25f * sh[0] / ((float)M * (float)DDIM);
    __syncthreads();
    float p = 0.f;
    float invM = 1.f / (float)M;
    for (int i = tid; i < C; i += 1024) {
        float pr = (float)g_counts[i] * invM;
        p += pr * logf(pr + 1e-10f);
    }
    sh[tid] = p; __syncthreads();
    for (int o = 512; o > 0; o >>= 1) { if (tid < o) sh[tid] += sh[tid + o]; __syncthreads(); }
    if (tid == 0 && hasStats) {
        outStats[0] = loss;
        outStats[1] = expf(-sh[0]);
    }
}

extern "C" void kernel_launch(void* const* d_in, const int* in_sizes, int n_in,
                              void* d_out, int out_size) {
    const float* z   = (const float*)d_in[0];
    const float* emb = (const float*)d_in[1];
    float* out = (float*)d_out;

    int M = in_sizes[0] / DDIM;   // 32768
    int C = in_sizes[1] / DDIM;   // 8192

    static int attr_done = 0;
    if (!attr_done) {
        cudaFuncSetAttribute(hmma_argmin_kernel, cudaFuncAttributeMaxDynamicSharedMemorySize, DYN_SMEM);
        cudaFuncSetAttribute(rescan_kernel, cudaFuncAttributeMaxDynamicSharedMemorySize, 512 * 33 * 4);
        attr_done = 1;
    }

    init_kernel<<<(MTOK + 255) / 256, 256>>>();
    {
        __half* zh; cudaGetSymbolAddress((void**)&zh, g_zh);
        __half* eh; cudaGetSymbolAddress((void**)&eh, g_eh);
        int nz4 = M * DDIM / 4, ne4 = C * DDIM / 4;
        convert_kernel<<<(nz4 + 255) / 256, 256>>>(z, zh, nz4);
        convert_kernel<<<(ne4 + 255) / 256, 256>>>(emb, eh, ne4);
    }
    enorm_kernel<<<C, 128>>>(emb);

    hmma_argmin_kernel<<<M / MT, 256, DYN_SMEM>>>(C);

    rescan_kernel<<<1024, 256, 512 * 33 * 4>>>(emb, z);

    long long zqN = (long long)M * DDIM;
    int writeCodes = (out_size >= zqN + M) ? 1 : 0;
    gather_kernel<<<M, 128>>>(z, emb, out, out + zqN, writeCodes);

    int hasStats = (out_size >= zqN + M + 2) ? 1 : 0;
    finalize_kernel<<<1, 1024>>>(out + zqN + M, M, C, hasStats);
}